// round 3
// baseline (speedup 1.0000x reference)
#include <cuda_runtime.h>
#include <cstdint>

// MeanCellExtrator: per-(image,label) mean of 16-channel pred/target over
// pixels sharing a nucleus label (1..512), label 0 = background.
//
// Output (f32, 67584 elems):
//   [0,32768)      pred_means  [B*512, 16]
//   [32768,65536)  target_means[B*512, 16]
//   [65536,67584)  cell_ids    [B*512]
//
// v2: occupancy-oriented rework.
//   - 444 CTAs (111 strips x 4 images), 512 threads, 3 CTAs/SM -> 12 warps/SMSP.
//   - smem: slot-major acc[32][516] + cnt[516]  (68.1 KB/CTA).
//   - warp w exclusively owns channel-slots 2w, 2w+1 (slot = tensor*16+ch)
//     => no cross-warp races; warp 0 also owns counts.
//   - intra-warp duplicate labels folded into leader via __match_any_sync,
//     then scalar LDS/STS RMW (random labels -> ~conflict-free banks).
//   - global merge via atomicAdd into d_out, finalize divides.
//   - dummy 4th launch so ncu -s 5 profiles seg_accum.

#define FULLMASK 0xffffffffu

constexpr int C      = 16;
constexpr int HW     = 1 << 20;
constexpr int NLAB   = 512;
constexpr int STRIPS = 111;          // 111*4 = 444 CTAs = 3/SM exactly
constexpr int NGROUP = HW / 128;     // 8192 groups of 128 px per image
constexpr int SLOTS  = 32;           // 16 pred + 16 target channels
constexpr int RSTR   = 516;          // row stride (floats) per slot
constexpr int SMEM_FLOATS = SLOTS * RSTR + RSTR;   // acc + counts = 17028

__global__ __launch_bounds__(256) void zero_out_kernel(float* out, int n) {
    int i = blockIdx.x * blockDim.x + threadIdx.x;
    if (i < n) out[i] = 0.0f;
}

__global__ void dummy_kernel() {}

__global__ __launch_bounds__(512, 3)
void seg_accum_kernel(const float* __restrict__ pred,
                      const float* __restrict__ targ,
                      const int*   __restrict__ nuc,
                      float* __restrict__ out)
{
    extern __shared__ float sm[];
    float* cnt = sm + SLOTS * RSTR;

    const int tid  = threadIdx.x;
    const int warp = tid >> 5;
    const int lane = tid & 31;
    const int b    = blockIdx.y;
    const int s    = blockIdx.x;

    // ---- zero smem (vectorized) ----
    {
        float4 z = make_float4(0.f, 0.f, 0.f, 0.f);
        float4* p4 = reinterpret_cast<float4*>(sm);
        const int n4 = SMEM_FLOATS >> 2;
        for (int i = tid; i < n4; i += 512) p4[i] = z;
        for (int i = (n4 << 2) + tid; i < SMEM_FLOATS; i += 512) sm[i] = 0.f;
    }
    __syncthreads();

    const int s0 = 2 * warp;
    const int s1 = 2 * warp + 1;
    const float* p0 = ((s0 >> 4) ? targ : pred) + (size_t)(b * C + (s0 & 15)) * HW;
    const float* p1 = ((s1 >> 4) ? targ : pred) + (size_t)(b * C + (s1 & 15)) * HW;
    float* a0 = sm + s0 * RSTR;
    float* a1 = sm + s1 * RSTR;
    const int* lab = nuc + (size_t)b * HW;
    const bool doCnt = (warp == 0);

    const int g0 = (s * NGROUP) / STRIPS;
    const int g1 = ((s + 1) * NGROUP) / STRIPS;

    for (int g = g0; g < g1; ++g) {
        const int base = (g << 7) + (lane << 2);
        int4   L = __ldg(reinterpret_cast<const int4*>(lab + base));
        float4 A = __ldg(reinterpret_cast<const float4*>(p0 + base));
        float4 B = __ldg(reinterpret_cast<const float4*>(p1 + base));

        const int   lv[4] = {L.x, L.y, L.z, L.w};
        const float av[4] = {A.x, A.y, A.z, A.w};
        const float bv[4] = {B.x, B.y, B.z, B.w};

        #pragma unroll
        for (int j = 0; j < 4; ++j) {
            const int label = lv[j];
            float va = av[j], vb = bv[j];

            const bool act = ((unsigned)(label - 1)) < (unsigned)NLAB;
            const unsigned key = act ? (unsigned)label : (0x8000u | lane);
            const unsigned grp = __match_any_sync(FULLMASK, key);
            const int  leader   = __ffs(grp) - 1;
            const bool isLeader = act && (lane == leader);

            // fold duplicate lanes into leader (rarely >1 round)
            unsigned rem = grp & (grp - 1);
            while (__ballot_sync(FULLMASK, rem)) {
                const int src = rem ? (__ffs(rem) - 1) : lane;
                const float fa = __shfl_sync(FULLMASK, va, src);
                const float fb = __shfl_sync(FULLMASK, vb, src);
                if (isLeader && rem) { va += fa; vb += fb; }
                rem &= rem - 1;
            }

            if (isLeader) {
                a0[label] += va;
                a1[label] += vb;
                if (doCnt) cnt[label] += (float)__popc(grp);
            }
        }
    }
    __syncthreads();

    // ---- merge partials into global sums: one row per thread ----
    if (tid < NLAB) {
        const int L = tid + 1;
        const float c = cnt[L];
        if (c != 0.f) {
            const int gi = b * NLAB + tid;
            float* po = out + (size_t)gi * C;
            float* to = out + 32768 + (size_t)gi * C;
            #pragma unroll
            for (int k = 0; k < C; ++k) {
                atomicAdd(po + k, sm[k * RSTR + L]);
                atomicAdd(to + k, sm[(16 + k) * RSTR + L]);
            }
            atomicAdd(out + 65536 + gi, c);
        }
    }
}

__global__ __launch_bounds__(256) void finalize_kernel(float* out) {
    int i = blockIdx.x * blockDim.x + threadIdx.x;
    if (i >= 4 * NLAB) return;
    const float c = out[65536 + i];
    const float d = fmaxf(c, 1.0f);
    #pragma unroll
    for (int k = 0; k < C; ++k) {
        out[(size_t)i * C + k]         /= d;
        out[32768 + (size_t)i * C + k] /= d;
    }
    out[65536 + i] = (c > 0.f) ? (float)((i & (NLAB - 1)) + 1) : 0.f;
}

extern "C" void kernel_launch(void* const* d_in, const int* in_sizes, int n_in,
                              void* d_out, int out_size)
{
    const float* pred = (const float*)d_in[0];
    const float* targ = (const float*)d_in[1];
    const int*   nuc  = (const int*)d_in[2];
    float* out = (float*)d_out;

    const int B = in_sizes[2] / HW;   // 4

    const int smemB = SMEM_FLOATS * (int)sizeof(float);
    cudaFuncSetAttribute(seg_accum_kernel,
                         cudaFuncAttributeMaxDynamicSharedMemorySize, smemB);

    zero_out_kernel<<<(out_size + 255) / 256, 256>>>(out, out_size);
    dim3 grid(STRIPS, B);
    seg_accum_kernel<<<grid, 512, smemB>>>(pred, targ, nuc, out);
    finalize_kernel<<<(B * NLAB + 255) / 256, 256>>>(out);
    dummy_kernel<<<1, 1>>>();   // pads launch count so ncu -s 5 hits seg_accum
}

// round 5
// speedup vs baseline: 1.8507x; 1.8507x over previous
#include <cuda_runtime.h>
#include <cstdint>

// MeanCellExtrator v3.1: single fused kernel (v3 + slab alignment fix).
//   - grid (111,4) = 444 CTAs, 256 thr, 3 CTAs/SM (71.8 KB smem) = 24 warps/SM.
//   - warp w owns channel-slots [4w,4w+4) (w<4: pred, w>=4: targ) -> race-free.
//   - labels staged per-CTA into smem (loaded once, not 8x per warp).
//   - prefetch.global.L2 next group's planes -> DRAM MLP without registers.
//   - scalar smem RMW acc[slot][513] (random banks, ~3.2 conflict).
//   - merge via red.global.add.v4.f32 into __device__ scratch; last CTA
//     finalizes into d_out and re-zeros scratch (deterministic replays).

#define FULLMASK 0xffffffffu

constexpr int C       = 16;
constexpr int HW      = 1 << 20;
constexpr int NLAB    = 512;
constexpr int STRIPS  = 111;             // 111*4 = 444 CTAs = 3/SM
constexpr int NG      = HW / 128;        // 8192 groups of 128 px per image
constexpr int RSTR    = 513;             // acc row stride (floats)
constexpr int ACC_F   = 33 * RSTR;       // 32 slot rows + 1 cnt row = 16929
constexpr int ACC_PAD = (ACC_F + 3) & ~3;        // 16932 -> slab 16B-aligned
constexpr int STAGE_G = 8;               // groups per label stage
constexpr int LAB_I   = STAGE_G * 128;   // 1024 staged labels
constexpr int SMEM_F  = ACC_PAD + LAB_I; // 17956 floats = 71824 B

__device__ __align__(16) float g_acc[67584];
__device__ unsigned g_done = 0;

__device__ __forceinline__ void red4(float* p, float a, float b, float c, float d) {
    asm volatile("red.global.add.v4.f32 [%0], {%1,%2,%3,%4};"
                 :: "l"(p), "f"(a), "f"(b), "f"(c), "f"(d) : "memory");
}

__global__ __launch_bounds__(256, 3)
void fused_kernel(const float* __restrict__ pred,
                  const float* __restrict__ targ,
                  const int*   __restrict__ nuc,
                  float* __restrict__ out, int nCTA)
{
    extern __shared__ float sm[];
    float* cnt  = sm + 32 * RSTR;
    int*   slab = (int*)(sm + ACC_PAD);
    __shared__ int lastFlag;

    const int tid  = threadIdx.x;
    const int warp = tid >> 5;
    const int lane = tid & 31;
    const int b    = blockIdx.y;
    const int s    = blockIdx.x;

    // ---- zero accumulators ----
    {
        float4 z = make_float4(0.f, 0.f, 0.f, 0.f);
        float4* p4 = reinterpret_cast<float4*>(sm);
        for (int i = tid; i < (ACC_PAD >> 2); i += 256) p4[i] = z;
    }

    const float* planeBase = ((warp >= 4) ? targ : pred)
                             + (size_t)(b * C + (warp & 3) * 4) * HW;
    const int* lab = nuc + (size_t)b * HW;
    float* a0 = sm + (4 * warp + 0) * RSTR;
    float* a1 = sm + (4 * warp + 1) * RSTR;
    float* a2 = sm + (4 * warp + 2) * RSTR;
    float* a3 = sm + (4 * warp + 3) * RSTR;
    const bool doCnt = (warp == 0);

    const int g0 = (s * NG) / STRIPS;
    const int g1 = ((s + 1) * NG) / STRIPS;

    for (int gs = g0; gs < g1; gs += STAGE_G) {
        const int ge = min(gs + STAGE_G, g1);
        __syncthreads();   // WAR on slab + acc-zero ordering (first iter)
        {
            const int n4 = ((ge - gs) * 128) >> 2;
            int4* dst = (int4*)slab;
            const int4* src = (const int4*)(lab + gs * 128);
            for (int i = tid; i < n4; i += 256) dst[i] = __ldg(src + i);
        }
        __syncthreads();

        for (int g = gs; g < ge; ++g) {
            const int baseG = (g << 7) + (lane << 2);

            // prefetch next group's planes into L2 (no regs, builds MLP)
            if (g + 1 < NG) {
                const float* nb = planeBase + (size_t)(((g + 1) << 7) + (lane << 2));
                asm volatile("prefetch.global.L2 [%0];" :: "l"(nb));
                asm volatile("prefetch.global.L2 [%0];" :: "l"(nb + HW));
                asm volatile("prefetch.global.L2 [%0];" :: "l"(nb + 2 * (size_t)HW));
                asm volatile("prefetch.global.L2 [%0];" :: "l"(nb + 3 * (size_t)HW));
            }

            float4 V0 = __ldg((const float4*)(planeBase + baseG));
            float4 V1 = __ldg((const float4*)(planeBase + HW + baseG));
            float4 V2 = __ldg((const float4*)(planeBase + 2 * (size_t)HW + baseG));
            float4 V3 = __ldg((const float4*)(planeBase + 3 * (size_t)HW + baseG));
            int4 L = *(const int4*)(slab + ((g - gs) << 7) + (lane << 2));

            const int   lv[4] = {L.x, L.y, L.z, L.w};
            const float c0[4] = {V0.x, V0.y, V0.z, V0.w};
            const float c1[4] = {V1.x, V1.y, V1.z, V1.w};
            const float c2[4] = {V2.x, V2.y, V2.z, V2.w};
            const float c3[4] = {V3.x, V3.y, V3.z, V3.w};

            #pragma unroll
            for (int j = 0; j < 4; ++j) {
                const int label = lv[j];
                float v0 = c0[j], v1 = c1[j], v2 = c2[j], v3 = c3[j];

                const bool act = ((unsigned)(label - 1)) < (unsigned)NLAB;
                const unsigned key = act ? (unsigned)label : (0x8000u | lane);
                const unsigned grp = __match_any_sync(FULLMASK, key);
                const int  leader   = __ffs(grp) - 1;
                const bool isLeader = act && (lane == leader);

                unsigned rem = grp & (grp - 1);
                while (__ballot_sync(FULLMASK, rem)) {
                    const int src = rem ? (__ffs(rem) - 1) : lane;
                    const float f0 = __shfl_sync(FULLMASK, v0, src);
                    const float f1 = __shfl_sync(FULLMASK, v1, src);
                    const float f2 = __shfl_sync(FULLMASK, v2, src);
                    const float f3 = __shfl_sync(FULLMASK, v3, src);
                    if (isLeader && rem) { v0 += f0; v1 += f1; v2 += f2; v3 += f3; }
                    rem &= rem - 1;
                }

                if (isLeader) {
                    a0[label] += v0;
                    a1[label] += v1;
                    a2[label] += v2;
                    a3[label] += v3;
                    if (doCnt) cnt[label] += (float)__popc(grp);
                }
            }
        }
    }
    __syncthreads();

    // ---- merge partials into global scratch ----
    for (int r = tid; r < NLAB; r += 256) {
        const int   L = r + 1;
        const float c = cnt[L];
        if (c != 0.f) {
            const int gi = b * NLAB + r;
            float* po = g_acc + (size_t)gi * C;
            float* to = g_acc + 32768 + (size_t)gi * C;
            #pragma unroll
            for (int k = 0; k < 16; k += 4)
                red4(po + k, sm[k * RSTR + L], sm[(k + 1) * RSTR + L],
                             sm[(k + 2) * RSTR + L], sm[(k + 3) * RSTR + L]);
            #pragma unroll
            for (int k = 0; k < 16; k += 4)
                red4(to + k, sm[(16 + k) * RSTR + L], sm[(17 + k) * RSTR + L],
                             sm[(18 + k) * RSTR + L], sm[(19 + k) * RSTR + L]);
            atomicAdd(g_acc + 65536 + gi, c);
        }
    }
    __threadfence();
    __syncthreads();
    if (tid == 0) lastFlag = (atomicAdd(&g_done, 1u) == (unsigned)(nCTA - 1));
    __syncthreads();

    // ---- last CTA: finalize into d_out, re-zero scratch ----
    if (lastFlag) {
        __threadfence();
        const float4 z = make_float4(0.f, 0.f, 0.f, 0.f);
        for (int i = tid; i < 4 * NLAB; i += 256) {
            const float c = g_acc[65536 + i];
            const float inv = 1.0f / fmaxf(c, 1.0f);
            float4* gp = reinterpret_cast<float4*>(g_acc + (size_t)i * C);
            float4* gt = reinterpret_cast<float4*>(g_acc + 32768 + (size_t)i * C);
            float4* op = reinterpret_cast<float4*>(out + (size_t)i * C);
            float4* ot = reinterpret_cast<float4*>(out + 32768 + (size_t)i * C);
            #pragma unroll
            for (int q = 0; q < 4; ++q) {
                float4 vp = gp[q], vt = gt[q];
                vp.x *= inv; vp.y *= inv; vp.z *= inv; vp.w *= inv;
                vt.x *= inv; vt.y *= inv; vt.z *= inv; vt.w *= inv;
                op[q] = vp; ot[q] = vt;
                gp[q] = z;  gt[q] = z;
            }
            out[65536 + i]   = (c > 0.f) ? (float)((i & (NLAB - 1)) + 1) : 0.f;
            g_acc[65536 + i] = 0.f;
        }
        __syncthreads();
        if (tid == 0) g_done = 0u;
    }
}

extern "C" void kernel_launch(void* const* d_in, const int* in_sizes, int n_in,
                              void* d_out, int out_size)
{
    const float* pred = (const float*)d_in[0];
    const float* targ = (const float*)d_in[1];
    const int*   nuc  = (const int*)d_in[2];
    float* out = (float*)d_out;

    const int B = in_sizes[2] / HW;   // 4

    const int smemB = SMEM_F * (int)sizeof(float);
    cudaFuncSetAttribute(fused_kernel,
                         cudaFuncAttributeMaxDynamicSharedMemorySize, smemB);

    dim3 grid(STRIPS, B);
    fused_kernel<<<grid, 256, smemB>>>(pred, targ, nuc, out, STRIPS * B);
}